// round 5
// baseline (speedup 1.0000x reference)
#include <cuda_runtime.h>
#include <math.h>

#define BB 16
#define CC 64
#define NN 2000
#define OCC 64
#define NP 2048   // padded size for bitonic sort / prefix index space

// ---------------- scratch (no allocations allowed) ----------------
__device__ float g_h[BB * NN * OCC];   // h[b][n][c]
__device__ float g_f1[BB * NN];
__device__ float g_f2[BB * NN];
__device__ float g_f2s[BB * NP];       // sorted f2 (ascending), padded +inf
__device__ int   g_perm[BB * NP];      // sorted rank -> original j

// ---------------- kernel A: h = x^T W ; f1 = x^T (W a1), f2 = x^T (W a2) ----------------
// grid (25, 16), block 256; 80 n-columns per block
__global__ void k_h(const float* __restrict__ inp, const float* __restrict__ W,
                    const float* __restrict__ a) {
    __shared__ float xs[80][CC + 1];
    __shared__ float Ws[CC][OCC + 1];
    __shared__ float as_[128];
    __shared__ float wa1[CC], wa2[CC];
    int b = blockIdx.y;
    int n0 = blockIdx.x * 80;
    int tid = threadIdx.x;

    for (int t = tid; t < CC * OCC; t += 256)
        Ws[t >> 6][t & 63] = W[t];
    for (int t = tid; t < 80 * CC; t += 256) {
        int c = t / 80, nl = t % 80;
        xs[nl][c] = inp[(b * CC + c) * NN + n0 + nl];
    }
    if (tid < 128) as_[tid] = a[tid];
    __syncthreads();

    if (tid < 128) {   // wa1 = W @ a1, wa2 = W @ a2
        int c = tid & 63;
        const float* av = as_ + (tid >> 6) * 64;
        float s = 0.f;
#pragma unroll
        for (int oc = 0; oc < 64; oc++)
            s = fmaf(Ws[c][oc], av[oc], s);
        if (tid < 64) wa1[c] = s; else wa2[c] = s;
    }

    for (int t = tid; t < 80 * OCC; t += 256) {
        int nl = t >> 6, c = t & 63;
        float acc = 0.f;
#pragma unroll
        for (int k = 0; k < CC; k++)
            acc = fmaf(xs[nl][k], Ws[k][c], acc);
        g_h[(b * NN + n0 + nl) * OCC + c] = acc;
    }
    __syncthreads();

    if (tid < 80) {
        float s1 = 0.f, s2 = 0.f;
#pragma unroll
        for (int k = 0; k < CC; k++) {
            float xv = xs[tid][k];
            s1 = fmaf(xv, wa1[k], s1);
            s2 = fmaf(xv, wa2[k], s2);
        }
        g_f1[b * NN + n0 + tid] = s1;
        g_f2[b * NN + n0 + tid] = s2;
    }
}

// ---------------- kernel C: per-batch bitonic sort of f2 (ascending) ----------------
__global__ void k_sort() {
    __shared__ float key[NP];
    __shared__ int   idx[NP];
    int b = blockIdx.x, tid = threadIdx.x;

    for (int i = tid; i < NP; i += 1024) {
        key[i] = (i < NN) ? g_f2[b * NN + i] : __int_as_float(0x7f800000);
        idx[i] = i;
    }
    __syncthreads();

    for (int kk = 2; kk <= NP; kk <<= 1) {
        for (int j = kk >> 1; j > 0; j >>= 1) {
#pragma unroll
            for (int half = 0; half < 2; half++) {
                int i = tid + half * 1024;
                int ixj = i ^ j;
                if (ixj > i) {
                    bool up = ((i & kk) == 0);
                    float ki = key[i], kx = key[ixj];
                    bool sw = up ? (ki > kx) : (ki < kx);
                    if (sw) {
                        key[i] = kx; key[ixj] = ki;
                        int t = idx[i]; idx[i] = idx[ixj]; idx[ixj] = t;
                    }
                }
            }
            __syncthreads();
        }
    }
    for (int i = tid; i < NP; i += 1024) {
        g_f2s[b * NP + i] = key[i];
        g_perm[b * NP + i] = idx[i];
    }
}

// ---------------- fused kernel: prefixes in smem + search + combine + store ----------------
// grid (8, 16): x = channel group (8 channels), y = batch. block 512.
#define ATILE 32
#define ANT   64                       // ANT*ATILE = 2048
#define OFF_PRE   0                     // float2 [2048][8]  131072 B
#define OFF_ZPRE  131072                // float2 [2048]      16384 B
#define OFF_FS    147456                // float  [2048]       8192 B
#define OFF_WS    155648                // float  [2048]       8192 B
#define OFF_WB    163840                // float  [2048]       8192 B
#define OFF_PIDX  172032                // int    [2048]       8192 B
#define OFF_TS    180224                // float2 [64][9]      4608 B
#define SMEM_ATT  184832

__global__ void k_att(float* __restrict__ out) {
    extern __shared__ char smraw[];
    float2* pre  = (float2*)(smraw + OFF_PRE);
    float2* zpre = (float2*)(smraw + OFF_ZPRE);
    float*  fs   = (float*) (smraw + OFF_FS);
    float*  wS   = (float*) (smraw + OFF_WS);
    float*  wB   = (float*) (smraw + OFF_WB);
    int*    pidx = (int*)   (smraw + OFF_PIDX);
    float2* ts   = (float2*)(smraw + OFF_TS);   // [64][9]: cl 0..7 = channel sums, 8 = Z

    int b  = blockIdx.y;
    int c0 = blockIdx.x * 8;
    int tid = threadIdx.x;

    // ---- stage A: load sorted keys/perm, compute weights ----
    for (int x = tid; x < NP; x += 512) {
        if (x < NN) {
            float f = g_f2s[b * NP + x];
            fs[x] = f;
            wS[x] = expf(0.01f * f);
            wB[x] = expf(f);
            pidx[x] = g_perm[b * NP + x];
        } else {
            fs[x] = __int_as_float(0x7f800000);
            wS[x] = 0.f; wB[x] = 0.f; pidx[x] = 0;
        }
    }
    __syncthreads();

    // ---- stage B: within-tile exclusive prefix chains ----
    {
        int t = tid >> 3, cl = tid & 7;
        int c = c0 + cl;
        const float* hb = g_h + (size_t)b * NN * OCC + c;
        int r0 = t * ATILE;
        float aS = 0.f, aB = 0.f;
#pragma unroll 4
        for (int r = 0; r < ATILE; r++) {
            int gr = r0 + r;
            pre[gr * 8 + cl] = make_float2(aS, aB);
            float hv = hb[(size_t)pidx[gr] * OCC];
            aS = fmaf(wS[gr], hv, aS);
            aB = fmaf(wB[gr], hv, aB);
        }
        ts[t * 9 + cl] = make_float2(aS, aB);
    }
    if (tid < ANT) {   // Z (weight-only) chains
        int r0 = tid * ATILE;
        float zS = 0.f, zB = 0.f;
#pragma unroll 4
        for (int r = 0; r < ATILE; r++) {
            int gr = r0 + r;
            zpre[gr] = make_float2(zS, zB);
            zS += wS[gr];
            zB += wB[gr];
        }
        ts[tid * 9 + 8] = make_float2(zS, zB);
    }
    __syncthreads();

    // ---- stage C: inclusive Hillis-Steele scan of tile sums (64 x 9 lanes) ----
    for (int off = 1; off < ANT; off <<= 1) {
        float2 v0, v1; bool d1 = false;
        int x0 = tid;
        int t0 = x0 / 9;
        {
            float2 a2 = ts[x0];
            float2 p2 = (t0 >= off) ? ts[x0 - off * 9] : make_float2(0.f, 0.f);
            v0 = make_float2(a2.x + p2.x, a2.y + p2.y);
        }
        int x1 = tid + 512;
        if (x1 < ANT * 9) {
            d1 = true;
            int t1 = x1 / 9;
            float2 a2 = ts[x1];
            float2 p2 = (t1 >= off) ? ts[x1 - off * 9] : make_float2(0.f, 0.f);
            v1 = make_float2(a2.x + p2.x, a2.y + p2.y);
        }
        __syncthreads();
        ts[x0] = v0;
        if (d1) ts[x1] = v1;
        __syncthreads();
    }

    // ---- stage D: per-row combine ----
    float2 ztot = ts[63 * 9 + 8];
#pragma unroll
    for (int p = 0; p < 4; p++) {
        int i = tid + p * 512;
        if (i >= NN) break;
        float f1v = g_f1[b * NN + i];
        float th = -f1v;
        int lo = 0, hi = NN;           // lower_bound: first idx with f2 >= -f1
        while (lo < hi) {
            int mid = (lo + hi) >> 1;
            if (fs[mid] < th) lo = mid + 1; else hi = mid;
        }
        int k = lo;
        int t = k >> 5;
        float A  = expf(f1v);
        float aa = expf(0.01f * f1v);

        float2 zofs = (t > 0) ? ts[(t - 1) * 9 + 8] : make_float2(0.f, 0.f);
        float2 zp = zpre[k];
        float pZS = zofs.x + zp.x;
        float pZB = zofs.y + zp.y;
        float den = A * (ztot.y - pZB) + aa * pZS;
        float rden = 1.f / den;

#pragma unroll
        for (int cl = 0; cl < 8; cl++) {
            float2 ofs = (t > 0) ? ts[(t - 1) * 9 + cl] : make_float2(0.f, 0.f);
            float2 tot = ts[63 * 9 + cl];
            float2 pp = pre[k * 8 + cl];
            float pS = ofs.x + pp.x;
            float pB = ofs.y + pp.y;
            float num = A * (tot.y - pB) + aa * pS;
            out[((size_t)b * OCC + c0 + cl) * NN + i] = fmaxf(num * rden, 0.f);
        }
    }
}

// ---------------- launch ----------------
extern "C" void kernel_launch(void* const* d_in, const int* in_sizes, int n_in,
                              void* d_out, int out_size) {
    const float* inp = (const float*)d_in[0];   // (16, 64, 2000)
    const float* W   = (const float*)d_in[1];   // (64, 64)
    const float* a   = (const float*)d_in[2];   // (128, 1)
    // d_in[3] = GL : unused (softmax output strictly positive -> adjacency mask is a no-op)
    float* out = (float*)d_out;                 // (16, 64, 2000)

    static int smem_set = 0;
    if (!smem_set) {
        cudaFuncSetAttribute(k_att, cudaFuncAttributeMaxDynamicSharedMemorySize, SMEM_ATT);
        smem_set = 1;
    }

    k_h   <<<dim3(25, BB), 256>>>(inp, W, a);
    k_sort<<<BB, 1024>>>();
    k_att <<<dim3(8, BB), 512, SMEM_ATT>>>(out);
}

// round 6
// speedup vs baseline: 1.2780x; 1.2780x over previous
#include <cuda_runtime.h>
#include <math.h>

#define BB 16
#define CC 64
#define NN 2000
#define OCC 64
#define NP 2048   // padded size for bitonic sort
#define TILE 128
#define NT 16     // NT*TILE = 2048 >= NN
#define KP 2048   // prefix index space

// ---------------- scratch (no allocations allowed) ----------------
__device__ float  g_h[BB * NN * OCC];    // h[b][n][c]
__device__ float  g_f1[BB * NN];
__device__ float  g_f2[BB * NN];
__device__ float  g_f2s[BB * NP];        // sorted f2 (ascending), padded +inf
__device__ int    g_perm[BB * NP];       // sorted rank -> original j
__device__ float2 g_pre[BB * KP * OCC];  // within-tile excl prefix {S=exp(.01 f2)*h, B=exp(f2)*h}
__device__ float2 g_preZ[BB * KP];       // within-tile excl prefix of weights {S,B}
__device__ float2 g_ts[BB * NT * OCC];   // per-tile sums {S,B}
__device__ float2 g_tsZ[BB * NT];        // per-tile weight sums {S,B}

// ---------------- kernel A: h = x^T W ; f1 = x^T (W a1), f2 = x^T (W a2) ----------------
// grid (25, 16), block 256; 80 n-columns per block; 5n x 4c register tile per thread
__global__ void k_h(const float* __restrict__ inp, const float* __restrict__ W,
                    const float* __restrict__ a) {
    __shared__ float xs[80][CC + 1];     // [nl][k]
    __shared__ float Ws[CC][OCC + 1];    // [k][c]
    __shared__ float as_[128];
    __shared__ float wa1[CC], wa2[CC];
    int b = blockIdx.y;
    int n0 = blockIdx.x * 80;
    int tid = threadIdx.x;

    for (int t = tid; t < CC * OCC; t += 256)
        Ws[t >> 6][t & 63] = W[t];
    for (int t = tid; t < 80 * CC; t += 256) {
        int c = t / 80, nl = t % 80;
        xs[nl][c] = inp[(b * CC + c) * NN + n0 + nl];
    }
    if (tid < 128) as_[tid] = a[tid];
    __syncthreads();

    if (tid < 128) {   // wa1 = W @ a1, wa2 = W @ a2 (conflict-free: stride-65 rows)
        int c = tid & 63;
        const float* av = as_ + (tid >> 6) * 64;
        float s = 0.f;
#pragma unroll
        for (int oc = 0; oc < 64; oc++)
            s = fmaf(Ws[c][oc], av[oc], s);
        if (tid < 64) wa1[c] = s; else wa2[c] = s;
    }

    // ---- register-tiled GEMM: thread owns rows nl0..nl0+4, cols c0..c0+3 ----
    {
        int cg = tid & 15, ng = tid >> 4;
        int c0 = cg * 4, nl0 = ng * 5;
        float4 acc0 = make_float4(0.f, 0.f, 0.f, 0.f);
        float4 acc1 = acc0, acc2 = acc0, acc3 = acc0, acc4 = acc0;
#pragma unroll 8
        for (int k = 0; k < CC; k++) {
            float w0 = Ws[k][c0], w1 = Ws[k][c0 + 1], w2 = Ws[k][c0 + 2], w3 = Ws[k][c0 + 3];
            float x0 = xs[nl0][k], x1 = xs[nl0 + 1][k], x2 = xs[nl0 + 2][k],
                  x3 = xs[nl0 + 3][k], x4 = xs[nl0 + 4][k];
            acc0.x = fmaf(x0, w0, acc0.x); acc0.y = fmaf(x0, w1, acc0.y);
            acc0.z = fmaf(x0, w2, acc0.z); acc0.w = fmaf(x0, w3, acc0.w);
            acc1.x = fmaf(x1, w0, acc1.x); acc1.y = fmaf(x1, w1, acc1.y);
            acc1.z = fmaf(x1, w2, acc1.z); acc1.w = fmaf(x1, w3, acc1.w);
            acc2.x = fmaf(x2, w0, acc2.x); acc2.y = fmaf(x2, w1, acc2.y);
            acc2.z = fmaf(x2, w2, acc2.z); acc2.w = fmaf(x2, w3, acc2.w);
            acc3.x = fmaf(x3, w0, acc3.x); acc3.y = fmaf(x3, w1, acc3.y);
            acc3.z = fmaf(x3, w2, acc3.z); acc3.w = fmaf(x3, w3, acc3.w);
            acc4.x = fmaf(x4, w0, acc4.x); acc4.y = fmaf(x4, w1, acc4.y);
            acc4.z = fmaf(x4, w2, acc4.z); acc4.w = fmaf(x4, w3, acc4.w);
        }
        float4* hrow = (float4*)(g_h + (size_t)(b * NN + n0 + nl0) * OCC + c0);
        size_t rs = OCC / 4;
        hrow[0] = acc0; hrow[rs] = acc1; hrow[2 * rs] = acc2;
        hrow[3 * rs] = acc3; hrow[4 * rs] = acc4;
    }
    __syncthreads();

    if (tid < 80) {   // f1/f2 dot products
        float s1 = 0.f, s2 = 0.f;
#pragma unroll
        for (int k = 0; k < CC; k++) {
            float xv = xs[tid][k];
            s1 = fmaf(xv, wa1[k], s1);
            s2 = fmaf(xv, wa2[k], s2);
        }
        g_f1[b * NN + n0 + tid] = s1;
        g_f2[b * NN + n0 + tid] = s2;
    }
}

// ---------------- kernel C: per-batch bitonic sort of f2 (ascending) ----------------
__global__ void k_sort() {
    __shared__ float key[NP];
    __shared__ int   idx[NP];
    int b = blockIdx.x, tid = threadIdx.x;

    for (int i = tid; i < NP; i += 1024) {
        key[i] = (i < NN) ? g_f2[b * NN + i] : __int_as_float(0x7f800000);
        idx[i] = i;
    }
    __syncthreads();

    for (int kk = 2; kk <= NP; kk <<= 1) {
        for (int j = kk >> 1; j > 0; j >>= 1) {
#pragma unroll
            for (int half = 0; half < 2; half++) {
                int i = tid + half * 1024;
                int ixj = i ^ j;
                if (ixj > i) {
                    bool up = ((i & kk) == 0);
                    float ki = key[i], kx = key[ixj];
                    bool sw = up ? (ki > kx) : (ki < kx);
                    if (sw) {
                        key[i] = kx; key[ixj] = ki;
                        int t = idx[i]; idx[i] = idx[ixj]; idx[ixj] = t;
                    }
                }
            }
            __syncthreads();
        }
    }
    for (int i = tid; i < NP; i += 1024) {
        g_f2s[b * NP + i] = key[i];
        g_perm[b * NP + i] = idx[i];
    }
}

// ---------------- kernel D: within-tile exclusive prefixes + tile sums ----------------
// grid (NT, BB), block 256
__global__ void k_tile() {
    __shared__ float hs[TILE][OCC];
    __shared__ float wS[TILE], wB[TILE];
    __shared__ int   pidx[TILE];
    int b = blockIdx.y, t = blockIdx.x, tid = threadIdx.x;
    int r0 = t * TILE;

    if (tid < TILE) {
        int gp = r0 + tid;
        if (gp < NN) {
            float f = g_f2s[b * NP + gp];
            wS[tid] = expf(0.01f * f);
            wB[tid] = expf(f);
            pidx[tid] = g_perm[b * NP + gp];
        } else {
            wS[tid] = 0.f; wB[tid] = 0.f; pidx[tid] = 0;
        }
    }
    __syncthreads();
    for (int x = tid; x < TILE * 16; x += 256) {
        int r = x >> 4, q = x & 15;
        reinterpret_cast<float4*>(hs[r])[q] =
            reinterpret_cast<const float4*>(g_h + (size_t)(b * NN + pidx[r]) * OCC)[q];
    }
    __syncthreads();

    if (tid < 64) {
        int c = tid;
        float aS = 0.f, aB = 0.f;
#pragma unroll 4
        for (int r = 0; r < TILE; r++) {
            g_pre[(size_t)(b * KP + r0 + r) * OCC + c] = make_float2(aS, aB);
            float hv = hs[r][c];
            aS = fmaf(wS[r], hv, aS);
            aB = fmaf(wB[r], hv, aB);
        }
        g_ts[(b * NT + t) * OCC + c] = make_float2(aS, aB);
    } else if (tid == 64) {
        float zS = 0.f, zB = 0.f;
#pragma unroll 4
        for (int r = 0; r < TILE; r++) {
            g_preZ[b * KP + r0 + r] = make_float2(zS, zB);
            zS += wS[r];
            zB += wB[r];
        }
        g_tsZ[b * NT + t] = make_float2(zS, zB);
    }
}

// ---------------- kernel E: search + combine + relu + transpose (80 rows / block) ----------------
// grid (25, 16), block (64, 16)
__global__ void k_out(float* __restrict__ out) {
    __shared__ float  fs[NN];
    __shared__ float  sm[80][OCC + 1];
    __shared__ float2 to[NT + 1][OCC];
    __shared__ float  zpreS[NT + 1], zpreB[NT + 1];
    __shared__ int    kks[80];
    __shared__ float  f1s[80];

    int b = blockIdx.y;
    int i0 = blockIdx.x * 80;
    int c = threadIdx.x, il = threadIdx.y;
    int tid = il * 64 + c;

    for (int x = tid; x < NN; x += 1024)
        fs[x] = g_f2s[b * NP + x];
    if (tid < 80) f1s[tid] = g_f1[b * NN + i0 + tid];

    if (tid >= 128 && tid < 192) {
        int ch = tid - 128;
        float aS = 0.f, aB = 0.f;
#pragma unroll
        for (int t2 = 0; t2 < NT; t2++) {
            to[t2][ch] = make_float2(aS, aB);
            float2 v = g_ts[(b * NT + t2) * OCC + ch];
            aS += v.x; aB += v.y;
        }
        to[NT][ch] = make_float2(aS, aB);
    } else if (tid == 192) {
        float aS = 0.f, aB = 0.f;
#pragma unroll
        for (int t2 = 0; t2 < NT; t2++) {
            zpreS[t2] = aS; zpreB[t2] = aB;
            float2 z = g_tsZ[b * NT + t2];
            aS += z.x; aB += z.y;
        }
        zpreS[NT] = aS; zpreB[NT] = aB;
    }
    __syncthreads();

    if (tid < 80) {
        float th = -f1s[tid];
        int lo = 0, hi = NN;
        while (lo < hi) {
            int mid = (lo + hi) >> 1;
            if (fs[mid] < th) lo = mid + 1; else hi = mid;
        }
        kks[tid] = lo;
    }
    __syncthreads();

#pragma unroll
    for (int g = 0; g < 5; g++) {
        int rl = g * 16 + il;
        int k = kks[rl];
        int t = k >> 7;
        float f1v = f1s[rl];
        float A  = expf(f1v);
        float aa = expf(0.01f * f1v);

        float2 pre  = g_pre[(size_t)(b * KP + k) * OCC + c];
        float2 preZ = g_preZ[b * KP + k];
        float2 tov  = to[t][c];
        float2 tot  = to[NT][c];

        float pS  = tov.x + pre.x;
        float pB  = tov.y + pre.y;
        float pZS = zpreS[t] + preZ.x;
        float pZB = zpreB[t] + preZ.y;

        float num = A * (tot.y - pB)      + aa * pS;
        float den = A * (zpreB[NT] - pZB) + aa * pZS;
        sm[rl][c] = fmaxf(num / den, 0.f);
    }
    __syncthreads();

#pragma unroll
    for (int e = tid; e < OCC * 80; e += 1024) {
        int c2 = e / 80, i2 = e % 80;
        out[(b * OCC + c2) * NN + i0 + i2] = sm[i2][c2];
    }
}

// ---------------- launch ----------------
extern "C" void kernel_launch(void* const* d_in, const int* in_sizes, int n_in,
                              void* d_out, int out_size) {
    const float* inp = (const float*)d_in[0];   // (16, 64, 2000)
    const float* W   = (const float*)d_in[1];   // (64, 64)
    const float* a   = (const float*)d_in[2];   // (128, 1)
    // d_in[3] = GL : unused (softmax output strictly positive -> adjacency mask is a no-op)
    float* out = (float*)d_out;                 // (16, 64, 2000)

    k_h   <<<dim3(25, BB), 256>>>(inp, W, a);
    k_sort<<<BB, 1024>>>();
    k_tile<<<dim3(NT, BB), 256>>>();
    k_out <<<dim3(25, BB), dim3(64, 16)>>>(out);
}